// round 6
// baseline (speedup 1.0000x reference)
#include <cuda_runtime.h>

// Problem constants (fixed by setup_inputs)
#define BB    16
#define CIN   64
#define COUT  64
#define HH    224
#define WW    224
#define PHH   32
#define PWW   32
#define PLANE   (HH * WW)
#define PLANE4  (PLANE / 4)      // 12544 float4s per plane
#define W4      (WW / 4)         // 56

// Conv tiling: CTA = (batch, 8-cout tile, 16-row tile); thread = 2 px x 8 couts
#define CIN_T 8
#define CO_T  8
#define OH_T  16
#define CONV_BLOCKS (BB * (COUT / CO_T) * (PHH / OH_T))  // 16*8*2 = 256
#define HALVES 2
#define HALF_ROWS (HH / HALVES)                          // 112
#define COPY_BLOCKS (BB * COUT * HALVES)                 // 2048
#define NTHREADS 256

#define S_R 36                       // padded row stride (floats)
#define S_C (18 * S_R)               // 648 floats per cin plane (18 rows)

__global__ __launch_bounds__(NTHREADS, 4)
void inc_conv_fused_kernel(const float* __restrict__ in,      // (B,Cin,H,W)
                           const float* __restrict__ wgt,     // (Cout,Cin,3,3)
                           const float* __restrict__ bias,    // (Cout)
                           const float* __restrict__ src_out, // (B,Cout,H,W)
                           const int*   __restrict__ locs,    // (B,2) [y,x]
                           float*       __restrict__ dst)     // (B,Cout,H,W)
{
    const int tid = threadIdx.x;

    if (blockIdx.x >= CONV_BLOCKS) {
        // ------------- COPY ROLE: one half-plane (112 rows) per CTA -------------
        const int id    = blockIdx.x - CONV_BLOCKS;   // plane*2 + half
        const int plane = id >> 1;                    // b*64 + c
        const int half  = id & 1;
        const int b     = plane >> 6;
        const int py    = __ldg(&locs[2 * b]);
        const int px    = __ldg(&locs[2 * b + 1]);

        const float4* __restrict__ s4 = (const float4*)src_out + (size_t)plane * PLANE4;
        float4*       __restrict__ d4 = (float4*)dst          + (size_t)plane * PLANE4;

        const int r0 = half * HALF_ROWS;
        const int r1 = r0 + HALF_ROWS;
        const int pr0 = max(py, r0);
        const int pr1 = min(py + PHH, r1);
        const int np  = max(0, pr1 - pr0);
        const int clean  = (HALF_ROWS - np) * W4;
        const int splitl = (np > 0 ? (pr0 - r0) : HALF_ROWS) * W4;
        const int skip   = np * W4;
        const int base   = r0 * W4;

        int i = tid;
        if (i + 3 * NTHREADS < clean) {
            int k[4]; float4 v[4];
            #pragma unroll
            for (int u = 0; u < 4; ++u) {
                const int ii = i + u * NTHREADS;
                k[u] = base + (ii < splitl ? ii : ii + skip);
            }
            #pragma unroll
            for (int u = 0; u < 4; ++u) v[u] = __ldcs(s4 + k[u]);

            for (i += 4 * NTHREADS; i + 3 * NTHREADS < clean; i += 4 * NTHREADS) {
                int kn[4]; float4 vn[4];
                #pragma unroll
                for (int u = 0; u < 4; ++u) {
                    const int ii = i + u * NTHREADS;
                    kn[u] = base + (ii < splitl ? ii : ii + skip);
                }
                #pragma unroll
                for (int u = 0; u < 4; ++u) vn[u] = __ldcs(s4 + kn[u]);
                #pragma unroll
                for (int u = 0; u < 4; ++u) __stcs(d4 + k[u], v[u]);
                #pragma unroll
                for (int u = 0; u < 4; ++u) { k[u] = kn[u]; v[u] = vn[u]; }
            }
            #pragma unroll
            for (int u = 0; u < 4; ++u) __stcs(d4 + k[u], v[u]);
        }
        for (; i < clean; i += NTHREADS) {
            const int k = base + (i < splitl ? i : i + skip);
            __stcs(d4 + k, __ldcs(s4 + k));
        }

        // patch rows in this half: mask patch columns
        const int pbase = pr0 * W4;
        #pragma unroll 1
        for (int t = tid; t < skip; t += NTHREADS) {
            const int j  = t % W4;
            const int w0 = j * 4;
            const int k  = pbase + t;
            const bool overlap = (w0 + 3 >= px) && (w0 <= px + PWW - 1);
            if (!overlap) {
                __stcs(d4 + k, __ldcs(s4 + k));
            } else {
                const bool covered = (w0 >= px) && (w0 + 3 <= px + PWW - 1);
                if (!covered) {
                    const float4 v = __ldcs(s4 + k);
                    float* d = (float*)(d4 + k);
                    const float* sv = (const float*)&v;
                    #pragma unroll
                    for (int jj = 0; jj < 4; ++jj) {
                        const unsigned dw = (unsigned)(w0 + jj - px);
                        if (dw >= PWW) d[jj] = sv[jj];
                    }
                }
            }
        }
        return;
    }

    // ------------------- CONV ROLE: 2 px x 8 couts per thread -------------------
    __shared__ float s_in[CIN_T * S_C];          // 8*648*4 = 20736 B
    __shared__ float s_w[CIN_T * 9 * CO_T];      // 576*4   =  2304 B

    const int conv_id = blockIdx.x;
    const int b       = conv_id >> 4;            // 16 blocks per batch
    const int rem     = conv_id & 15;
    const int co0     = (rem >> 1) * CO_T;       // 8 cout tiles
    const int oh0     = (rem & 1) * OH_T;        // 2 row tiles

    const int y = locs[2 * b];
    const int x = locs[2 * b + 1];

    const int tx = tid & 15;       // column pair: output cols 2tx, 2tx+1
    const int ty = tid >> 4;       // output row: oh0 + ty  (ty 0..15)

    float acc[16];                 // [px][co] : 2 x 8
    #pragma unroll
    for (int c = 0; c < 16; ++c) acc[c] = 0.0f;

    const int gr0 = y + oh0 - 1;   // input tile origin (unpadded)
    const int gc0 = x - 1;

    for (int ci0 = 0; ci0 < CIN; ci0 += CIN_T) {
        // input chunk: CIN_T x 18 x 34
        #pragma unroll 1
        for (int t = tid; t < CIN_T * 18 * 34; t += NTHREADS) {
            const int ci  = t / (18 * 34);
            const int rem2 = t - ci * (18 * 34);
            const int r   = rem2 / 34;
            const int c   = rem2 - r * 34;
            const int gr  = gr0 + r;
            const int gc  = gc0 + c;
            float v = 0.0f;
            if (gr >= 0 && gc >= 0)   // high side provably in-bounds
                v = in[((size_t)(b * CIN + ci0 + ci) * HH + gr) * WW + gc];
            s_in[ci * S_C + r * S_R + c] = v;
        }
        // weights transposed: s_w[(ci*9+k)*CO_T + co]
        for (int t = tid; t < CO_T * CIN_T * 9; t += NTHREADS) {
            const int co = t / (CIN_T * 9);
            const int r2 = t - co * (CIN_T * 9);
            const int ci = r2 / 9;
            const int k  = r2 - ci * 9;
            s_w[(ci * 9 + k) * CO_T + co] =
                wgt[((co0 + co) * CIN + ci0 + ci) * 9 + k];
        }
        __syncthreads();

        #pragma unroll 1
        for (int ci = 0; ci < CIN_T; ++ci) {
            // input window: rows ty..ty+2, cols 2tx..2tx+3 (even col => float2-aligned)
            const float* base2 = &s_in[ci * S_C + ty * S_R + 2 * tx];
            float iv[3][4];
            #pragma unroll
            for (int r = 0; r < 3; ++r) {
                const float2 a = *(const float2*)(base2 + r * S_R);
                const float2 c2 = *(const float2*)(base2 + r * S_R + 2);
                iv[r][0] = a.x; iv[r][1] = a.y; iv[r][2] = c2.x; iv[r][3] = c2.y;
            }
            #pragma unroll
            for (int kh = 0; kh < 3; ++kh) {
                #pragma unroll
                for (int kw = 0; kw < 3; ++kw) {
                    const float4* wp = (const float4*)&s_w[(ci * 9 + kh * 3 + kw) * CO_T];
                    const float4 w0 = wp[0], w1 = wp[1];
                    const float v0 = iv[kh][kw];       // pixel 0 (col 2tx)
                    const float v1 = iv[kh][kw + 1];   // pixel 1 (col 2tx+1)
                    acc[0]  += v0 * w0.x;  acc[1]  += v0 * w0.y;
                    acc[2]  += v0 * w0.z;  acc[3]  += v0 * w0.w;
                    acc[4]  += v0 * w1.x;  acc[5]  += v0 * w1.y;
                    acc[6]  += v0 * w1.z;  acc[7]  += v0 * w1.w;
                    acc[8]  += v1 * w0.x;  acc[9]  += v1 * w0.y;
                    acc[10] += v1 * w0.z;  acc[11] += v1 * w0.w;
                    acc[12] += v1 * w1.x;  acc[13] += v1 * w1.y;
                    acc[14] += v1 * w1.z;  acc[15] += v1 * w1.w;
                }
            }
        }
        __syncthreads();
    }

    // store: 2 px x 8 couts (+bias)
    const int oy  = y + oh0 + ty;
    const int ox0 = x + 2 * tx;
    #pragma unroll
    for (int co = 0; co < CO_T; ++co) {
        const float bv = bias[co0 + co];
        float* drow = &dst[((size_t)(b * COUT + co0 + co) * HH + oy) * WW + ox0];
        drow[0] = acc[co]     + bv;
        drow[1] = acc[8 + co] + bv;
    }
}

extern "C" void kernel_launch(void* const* d_in, const int* in_sizes, int n_in,
                              void* d_out, int out_size) {
    const float* in_tensor  = (const float*)d_in[0];
    const float* weights    = (const float*)d_in[1];
    const float* biases     = (const float*)d_in[2];
    const float* out_stale  = (const float*)d_in[3];
    const int*   locs       = (const int*)d_in[4];
    float*       out        = (float*)d_out;

    inc_conv_fused_kernel<<<CONV_BLOCKS + COPY_BLOCKS, NTHREADS>>>(
        in_tensor, weights, biases, out_stale, locs, out);
}

// round 7
// speedup vs baseline: 1.0485x; 1.0485x over previous
#include <cuda_runtime.h>

// Problem constants (fixed by setup_inputs)
#define BB    16
#define CIN   64
#define COUT  64
#define HH    224
#define WW    224
#define PHH   32
#define PWW   32
#define PLANE   (HH * WW)
#define PLANE4  (PLANE / 4)      // 12544 float4s per plane
#define W4      (WW / 4)         // 56

// Conv tiling (R5/R2 proven shape, f32x2 math)
#define CIN_T 16
#define CO_T  16
#define OH_T  8
#define CONV_BLOCKS (BB * (COUT / CO_T) * (PHH / OH_T))  // 256
#define HALVES 2
#define HALF_ROWS (HH / HALVES)                          // 112
#define COPY_BLOCKS (BB * COUT * HALVES)                 // 2048
#define NTHREADS 256

#define SIN_STRIDE_R 36
#define SIN_STRIDE_C (10 * SIN_STRIDE_R)

__device__ __forceinline__ unsigned long long pack2(float v) {
    unsigned long long r;
    asm("mov.b64 %0, {%1, %1};" : "=l"(r) : "f"(v));
    return r;
}
__device__ __forceinline__ void ffma2(unsigned long long& acc,
                                      unsigned long long w,
                                      unsigned long long v) {
    asm("fma.rn.f32x2 %0, %1, %2, %0;" : "+l"(acc) : "l"(w), "l"(v));
}

__global__ __launch_bounds__(NTHREADS, 4)
void inc_conv_fused_kernel(const float* __restrict__ in,      // (B,Cin,H,W)
                           const float* __restrict__ wgt,     // (Cout,Cin,3,3)
                           const float* __restrict__ bias,    // (Cout)
                           const float* __restrict__ src_out, // (B,Cout,H,W)
                           const int*   __restrict__ locs,    // (B,2) [y,x]
                           float*       __restrict__ dst)     // (B,Cout,H,W)
{
    const int tid = threadIdx.x;

    if (blockIdx.x >= CONV_BLOCKS) {
        // ------------- COPY ROLE: one half-plane (112 rows) per CTA (R5) -------------
        const int id    = blockIdx.x - CONV_BLOCKS;   // plane*2 + half
        const int plane = id >> 1;                    // b*64 + c
        const int half  = id & 1;
        const int b     = plane >> 6;
        const int py    = __ldg(&locs[2 * b]);
        const int px    = __ldg(&locs[2 * b + 1]);

        const float4* __restrict__ s4 = (const float4*)src_out + (size_t)plane * PLANE4;
        float4*       __restrict__ d4 = (float4*)dst          + (size_t)plane * PLANE4;

        const int r0 = half * HALF_ROWS;
        const int r1 = r0 + HALF_ROWS;
        const int pr0 = max(py, r0);
        const int pr1 = min(py + PHH, r1);
        const int np  = max(0, pr1 - pr0);
        const int clean  = (HALF_ROWS - np) * W4;
        const int splitl = (np > 0 ? (pr0 - r0) : HALF_ROWS) * W4;
        const int skip   = np * W4;
        const int base   = r0 * W4;

        int i = tid;
        if (i + 3 * NTHREADS < clean) {
            int k[4]; float4 v[4];
            #pragma unroll
            for (int u = 0; u < 4; ++u) {
                const int ii = i + u * NTHREADS;
                k[u] = base + (ii < splitl ? ii : ii + skip);
            }
            #pragma unroll
            for (int u = 0; u < 4; ++u) v[u] = __ldcs(s4 + k[u]);

            for (i += 4 * NTHREADS; i + 3 * NTHREADS < clean; i += 4 * NTHREADS) {
                int kn[4]; float4 vn[4];
                #pragma unroll
                for (int u = 0; u < 4; ++u) {
                    const int ii = i + u * NTHREADS;
                    kn[u] = base + (ii < splitl ? ii : ii + skip);
                }
                #pragma unroll
                for (int u = 0; u < 4; ++u) vn[u] = __ldcs(s4 + kn[u]);
                #pragma unroll
                for (int u = 0; u < 4; ++u) __stcs(d4 + k[u], v[u]);
                #pragma unroll
                for (int u = 0; u < 4; ++u) { k[u] = kn[u]; v[u] = vn[u]; }
            }
            #pragma unroll
            for (int u = 0; u < 4; ++u) __stcs(d4 + k[u], v[u]);
        }
        for (; i < clean; i += NTHREADS) {
            const int k = base + (i < splitl ? i : i + skip);
            __stcs(d4 + k, __ldcs(s4 + k));
        }

        // patch rows in this half: mask patch columns
        const int pbase = pr0 * W4;
        #pragma unroll 1
        for (int t = tid; t < skip; t += NTHREADS) {
            const int j  = t % W4;
            const int w0 = j * 4;
            const int k  = pbase + t;
            const bool overlap = (w0 + 3 >= px) && (w0 <= px + PWW - 1);
            if (!overlap) {
                __stcs(d4 + k, __ldcs(s4 + k));
            } else {
                const bool covered = (w0 >= px) && (w0 + 3 <= px + PWW - 1);
                if (!covered) {
                    const float4 v = __ldcs(s4 + k);
                    float* d = (float*)(d4 + k);
                    const float* sv = (const float*)&v;
                    #pragma unroll
                    for (int jj = 0; jj < 4; ++jj) {
                        const unsigned dw = (unsigned)(w0 + jj - px);
                        if (dw >= PWW) d[jj] = sv[jj];
                    }
                }
            }
        }
        return;
    }

    // ------------------- CONV ROLE (R5 shape, f32x2 FFMA2) -------------------
    __shared__ float s_in[CIN_T * SIN_STRIDE_C];
    __shared__ __align__(16) float s_w[CIN_T * 9 * CO_T];

    const int conv_id = blockIdx.x;
    const int b       = conv_id >> 4;
    const int rem     = conv_id & 15;
    const int co0     = (rem >> 2) * CO_T;
    const int oh0     = (rem & 3) * OH_T;

    const int y = locs[2 * b];
    const int x = locs[2 * b + 1];

    const int oh_l = tid >> 5;
    const int ow   = tid & 31;

    // 8 packed f32x2 accumulators = 16 couts; pair j holds (co=2j lo, co=2j+1 hi)
    unsigned long long acc[8];
    #pragma unroll
    for (int c = 0; c < 8; ++c) acc[c] = 0ULL;

    const int gr0 = y + oh0 - 1;
    const int gc0 = x - 1;

    for (int ci0 = 0; ci0 < CIN; ci0 += CIN_T) {
        for (int t = tid; t < CIN_T * 10 * 34; t += NTHREADS) {
            const int ci = t / (10 * 34);
            const int r  = (t / 34) % 10;
            const int c  = t % 34;
            const int gr = gr0 + r;
            const int gc = gc0 + c;
            float v = 0.0f;
            if (gr >= 0 && gc >= 0)
                v = in[((size_t)(b * CIN + ci0 + ci) * HH + gr) * WW + gc];
            s_in[ci * SIN_STRIDE_C + r * SIN_STRIDE_R + c] = v;
        }
        for (int t = tid; t < CO_T * CIN_T * 9; t += NTHREADS) {
            const int co = t / (CIN_T * 9);
            const int r2 = t % (CIN_T * 9);
            const int ci = r2 / 9;
            const int k  = r2 % 9;
            s_w[(ci * 9 + k) * CO_T + co] =
                wgt[((co0 + co) * CIN + ci0 + ci) * 9 + k];
        }
        __syncthreads();

        #pragma unroll 4
        for (int ci = 0; ci < CIN_T; ++ci) {
            const float* ibase = &s_in[ci * SIN_STRIDE_C + oh_l * SIN_STRIDE_R + ow];
            #pragma unroll
            for (int kh = 0; kh < 3; ++kh) {
                const float i0 = ibase[kh * SIN_STRIDE_R + 0];
                const float i1 = ibase[kh * SIN_STRIDE_R + 1];
                const float i2 = ibase[kh * SIN_STRIDE_R + 2];
                #pragma unroll
                for (int kw = 0; kw < 3; ++kw) {
                    const float ivs = (kw == 0) ? i0 : ((kw == 1) ? i1 : i2);
                    const unsigned long long vv = pack2(ivs);
                    // 16 weights = 4 x LDS.128, each yielding two f32x2 lane-pairs
                    const ulonglong2* wp =
                        (const ulonglong2*)&s_w[(ci * 9 + kh * 3 + kw) * CO_T];
                    const ulonglong2 wa = wp[0], wb = wp[1],
                                     wc = wp[2], wd = wp[3];
                    ffma2(acc[0], wa.x, vv);  ffma2(acc[1], wa.y, vv);
                    ffma2(acc[2], wb.x, vv);  ffma2(acc[3], wb.y, vv);
                    ffma2(acc[4], wc.x, vv);  ffma2(acc[5], wc.y, vv);
                    ffma2(acc[6], wd.x, vv);  ffma2(acc[7], wd.y, vv);
                }
            }
        }
        __syncthreads();
    }

    // store patch outputs (+bias)
    const int oy = y + oh0 + oh_l;
    const int ox = x + ow;
    #pragma unroll
    for (int j = 0; j < 8; ++j) {
        float lo, hi;
        asm("mov.b64 {%0, %1}, %2;" : "=f"(lo), "=f"(hi) : "l"(acc[j]));
        const int coA = co0 + 2 * j;
        dst[((size_t)(b * COUT + coA) * HH + oy) * WW + ox]     = lo + bias[coA];
        dst[((size_t)(b * COUT + coA + 1) * HH + oy) * WW + ox] = hi + bias[coA + 1];
    }
}

extern "C" void kernel_launch(void* const* d_in, const int* in_sizes, int n_in,
                              void* d_out, int out_size) {
    const float* in_tensor  = (const float*)d_in[0];
    const float* weights    = (const float*)d_in[1];
    const float* biases     = (const float*)d_in[2];
    const float* out_stale  = (const float*)d_in[3];
    const int*   locs       = (const int*)d_in[4];
    float*       out        = (float*)d_out;

    inc_conv_fused_kernel<<<CONV_BLOCKS + COPY_BLOCKS, NTHREADS>>>(
        in_tensor, weights, biases, out_stale, locs, out);
}